// round 3
// baseline (speedup 1.0000x reference)
#include <cuda_runtime.h>

#define EPSQ 1e-7f
typedef unsigned long long ull;

__device__ __forceinline__ ull fma2(ull a, ull b, ull c) {
    ull d; asm("fma.rn.f32x2 %0, %1, %2, %3;" : "=l"(d) : "l"(a), "l"(b), "l"(c)); return d;
}
__device__ __forceinline__ void upk2(ull v, float& lo, float& hi) {
    asm("mov.b64 {%0,%1}, %2;" : "=f"(lo), "=f"(hi) : "l"(v));
}
__device__ __forceinline__ ull dup2(float x) {
    ull r; asm("mov.b64 %0, {%1,%1};" : "=l"(r) : "f"(x)); return r;
}

// scratch (static device globals; no runtime allocation)
__device__ float g_V0[64 * 512];                 // iter-0 V (c uniform), n-independent
__device__ float g_Vp[(size_t)4 * 64 * 32 * 512]; // per-chunk partial V  (16 MB)
__device__ float g_t [(size_t)64 * 32 * 512];     // t[b,n,d] = W_n . out[b,n,:]

// ---------------- V0[b,d] = (1/32) * sum_i U[b,i,d] ----------------
__global__ void k_sum0(const float* __restrict__ U) {
    int b = blockIdx.y, d0 = blockIdx.x * 64;
    int tid = threadIdx.x, dl = tid & 63, grp = tid >> 6;
    const float* base = U + (size_t)b * 1024 * 512 + d0 + dl;
    float a0 = 0.f, a1 = 0.f;
    #pragma unroll 4
    for (int i = grp; i < 1024; i += 8) {
        a0 += base[(size_t)i * 512];
        a1 += base[(size_t)(i + 4) * 512];
    }
    __shared__ float red[4][64];
    red[grp][dl] = a0 + a1;
    __syncthreads();
    if (tid < 64)
        g_V0[b * 512 + d0 + tid] =
            (red[0][tid] + red[1][tid] + red[2][tid] + red[3][tid]) * (1.0f / 32.0f);
}

// ---- out[b,n,dc] = squash_dc( sum_d V[b,n,d] * W[d, n*64+dc] ) ----
__global__ void __launch_bounds__(256) k_out(const float* __restrict__ W,
                                             float* __restrict__ out, int first) {
    int b0 = blockIdx.x * 8, n = blockIdx.y;
    int tid = threadIdx.x;
    __shared__ float V_s[8][512];
    __shared__ float sq[4][2][2];
    for (int idx = tid; idx < 8 * 512; idx += 256) {
        int bb = idx >> 9, d = idx & 511;
        float v;
        if (first) {
            v = g_V0[(b0 + bb) * 512 + d];
        } else {
            v = 0.f;
            #pragma unroll
            for (int ch = 0; ch < 4; ch++)
                v += g_Vp[(((size_t)ch * 64 + b0 + bb) * 32 + n) * 512 + d];
        }
        V_s[bb][d] = v;
    }
    __syncthreads();
    int dc = tid & 63, bq = tid >> 6;
    const float* wcol = W + n * 64 + dc;
    float p0[4] = {0.f, 0.f, 0.f, 0.f}, p1[4] = {0.f, 0.f, 0.f, 0.f};
    #pragma unroll 2
    for (int d = 0; d < 512; d += 4) {
        #pragma unroll
        for (int j = 0; j < 4; j++) {
            float w = wcol[(size_t)(d + j) * 2048];
            p0[j] = fmaf(V_s[bq][d + j], w, p0[j]);
            p1[j] = fmaf(V_s[bq + 4][d + j], w, p1[j]);
        }
    }
    float a0 = (p0[0] + p0[1]) + (p0[2] + p0[3]);
    float a1 = (p1[0] + p1[1]) + (p1[2] + p1[3]);
    float s0 = a0 * a0, s1 = a1 * a1;
    #pragma unroll
    for (int o = 16; o > 0; o >>= 1) {
        s0 += __shfl_xor_sync(0xffffffffu, s0, o);
        s1 += __shfl_xor_sync(0xffffffffu, s1, o);
    }
    int half = (tid >> 5) & 1;
    if ((tid & 31) == 0) { sq[bq][0][half] = s0; sq[bq][1][half] = s1; }
    __syncthreads();
    float inv0 = rsqrtf(sq[bq][0][0] + sq[bq][0][1] + EPSQ);
    float inv1 = rsqrtf(sq[bq][1][0] + sq[bq][1][1] + EPSQ);
    out[(size_t)(b0 + bq) * 2048 + n * 64 + dc]     = a0 * inv0;
    out[(size_t)(b0 + bq + 4) * 2048 + n * 64 + dc] = a1 * inv1;
}

// ---------- t[b,n,d] = sum_dc W[d, n*64+dc] * out[b,n,dc] ----------
__global__ void __launch_bounds__(256) k_t(const float* __restrict__ W,
                                           const float* __restrict__ out) {
    int n = blockIdx.x, b0 = blockIdx.y * 8;
    int tid = threadIdx.x;
    __shared__ float o_s[8][64];
    for (int idx = tid; idx < 512; idx += 256) {
        int bb = idx >> 6, dc = idx & 63;
        o_s[bb][dc] = out[(size_t)(b0 + bb) * 2048 + n * 64 + dc];
    }
    __syncthreads();
    int d0 = tid * 2;
    float acc[2][8];
    #pragma unroll
    for (int dd = 0; dd < 2; dd++)
        #pragma unroll
        for (int bb = 0; bb < 8; bb++) acc[dd][bb] = 0.f;
    #pragma unroll 2
    for (int dct = 0; dct < 16; dct++) {
        float4 w0 = *(const float4*)(W + (size_t)d0 * 2048 + n * 64 + dct * 4);
        float4 w1 = *(const float4*)(W + (size_t)(d0 + 1) * 2048 + n * 64 + dct * 4);
        #pragma unroll
        for (int bb = 0; bb < 8; bb++) {
            float4 o = *(const float4*)&o_s[bb][dct * 4];
            acc[0][bb] += (w0.x * o.x + w0.y * o.y) + (w0.z * o.z + w0.w * o.w);
            acc[1][bb] += (w1.x * o.x + w1.y * o.y) + (w1.z * o.z + w1.w * o.w);
        }
    }
    #pragma unroll
    for (int bb = 0; bb < 8; bb++) {
        g_t[((size_t)(b0 + bb) * 32 + n) * 512 + d0]     = acc[0][bb];
        g_t[((size_t)(b0 + bb) * 32 + n) * 512 + d0 + 1] = acc[1][bb];
    }
}

// ------- fused routing iteration: logits -> softmax -> partial V -------
// grid (4 i-chunks of 256, 64 b), 256 threads
__global__ void __launch_bounds__(256, 2) k_route(const float* __restrict__ U) {
    __shared__ ulonglong2 t4_s[32][32];  // [kt][n] float4-as-2xf32x2, 16 KB
    __shared__ float c_s[256][32];       // logits -> coupling coeffs, 32 KB

    int ch = blockIdx.x, b = blockIdx.y;
    int tid = threadIdx.x;
    const float* Ub = U + ((size_t)b * 1024 + ch * 256) * 512;
    const float* Tb = g_t + (size_t)b * 32 * 512;

    // ---------- phase A: L[i,n] = u[i,:].t[n,:]  (f32x2, k-packed) ----------
    int ti = tid >> 3, tn = tid & 7;
    int n0 = tn * 4;
    for (int ih = 0; ih < 2; ih++) {
        int i0 = ti * 4 + ih * 128;
        ull acc[4][4];
        #pragma unroll
        for (int p = 0; p < 4; p++)
            #pragma unroll
            for (int nn = 0; nn < 4; nn++) acc[p][nn] = 0ULL;
        for (int ks = 0; ks < 4; ks++) {
            int k0 = ks * 128;
            __syncthreads();
            for (int e = tid; e < 1024; e += 256) {
                int kt = e >> 5, n = e & 31;
                t4_s[kt][n] = *(const ulonglong2*)(Tb + (size_t)n * 512 + k0 + kt * 4);
            }
            __syncthreads();
            #pragma unroll 2
            for (int kt = 0; kt < 32; kt++) {
                ulonglong2 uv[4];
                #pragma unroll
                for (int p = 0; p < 4; p++)
                    uv[p] = *(const ulonglong2*)(Ub + (size_t)(i0 + p) * 512 + k0 + kt * 4);
                #pragma unroll
                for (int nn = 0; nn < 4; nn++) {
                    ulonglong2 tv = t4_s[kt][n0 + nn];
                    #pragma unroll
                    for (int p = 0; p < 4; p++) {
                        acc[p][nn] = fma2(uv[p].x, tv.x, acc[p][nn]);
                        acc[p][nn] = fma2(uv[p].y, tv.y, acc[p][nn]);
                    }
                }
            }
        }
        #pragma unroll
        for (int p = 0; p < 4; p++)
            #pragma unroll
            for (int nn = 0; nn < 4; nn++) {
                float f0, f1; upk2(acc[p][nn], f0, f1);
                c_s[i0 + p][n0 + nn] = f0 + f1;
            }
    }
    __syncthreads();

    // ---------- softmax over the 32 output capsules, per row i ----------
    {
        int w = tid >> 5, lane = tid & 31;
        for (int r = 0; r < 32; r++) {
            int row = w * 32 + r;
            float v = c_s[row][lane];
            float mx = v;
            #pragma unroll
            for (int o = 16; o > 0; o >>= 1)
                mx = fmaxf(mx, __shfl_xor_sync(0xffffffffu, mx, o));
            float e = __expf(v - mx);
            float sm = e;
            #pragma unroll
            for (int o = 16; o > 0; o >>= 1)
                sm += __shfl_xor_sync(0xffffffffu, sm, o);
            c_s[row][lane] = e / sm;
        }
    }
    __syncthreads();

    // ---------- phase B: Vp[n,d] = sum_i c[i,n]*u[i,d]  (f32x2) ----------
    int td = tid & 15, tq = tid >> 4;  // this thread: n in {tq, tq+16}, d = m*64 + td*4
    ull accB[2][8][2];
    #pragma unroll
    for (int s = 0; s < 2; s++)
        #pragma unroll
        for (int m = 0; m < 8; m++) { accB[s][m][0] = 0ULL; accB[s][m][1] = 0ULL; }
    #pragma unroll 2
    for (int i = 0; i < 256; i++) {
        ull cc0 = dup2(c_s[i][tq]);
        ull cc1 = dup2(c_s[i][tq + 16]);
        const ulonglong2* row = (const ulonglong2*)(Ub + (size_t)i * 512);
        #pragma unroll
        for (int m = 0; m < 8; m++) {
            ulonglong2 u = row[m * 16 + td];
            accB[0][m][0] = fma2(cc0, u.x, accB[0][m][0]);
            accB[0][m][1] = fma2(cc0, u.y, accB[0][m][1]);
            accB[1][m][0] = fma2(cc1, u.x, accB[1][m][0]);
            accB[1][m][1] = fma2(cc1, u.y, accB[1][m][1]);
        }
    }
    #pragma unroll
    for (int s = 0; s < 2; s++) {
        int n = tq + 16 * s;
        float* dst = g_Vp + (((size_t)ch * 64 + b) * 32 + n) * 512;
        #pragma unroll
        for (int m = 0; m < 8; m++) {
            ulonglong2 o; o.x = accB[s][m][0]; o.y = accB[s][m][1];
            *(ulonglong2*)(dst + m * 64 + td * 4) = o;
        }
    }
}

extern "C" void kernel_launch(void* const* d_in, const int* in_sizes, int n_in,
                              void* d_out, int out_size) {
    const float* U = (const float*)d_in[0];  // [64,1024,512]
    const float* W = (const float*)d_in[1];  // [1,512,2048]
    float* out = (float*)d_out;              // [64,32,64]

    k_sum0 <<<dim3(8, 64), 256>>>(U);
    k_out  <<<dim3(8, 32), 256>>>(W, out, 1);   // iter 0 (c uniform)
    k_t    <<<dim3(32, 8), 256>>>(W, out);
    k_route<<<dim3(4, 64), 256>>>(U);           // iter 1 routing
    k_out  <<<dim3(8, 32), 256>>>(W, out, 0);
    k_t    <<<dim3(32, 8), 256>>>(W, out);
    k_route<<<dim3(4, 64), 256>>>(U);           // iter 2 routing
    k_out  <<<dim3(8, 32), 256>>>(W, out, 0);   // final outputs
}

// round 10
// speedup vs baseline: 3.8885x; 3.8885x over previous
#include <cuda_runtime.h>
#include <cuda_bf16.h>
#include <cstdint>

#define EPSQ 1e-7f
typedef __nv_bfloat16 bf16;

// ---------------- static device scratch ----------------
__device__ bf16  g_Uh[(size_t)64*1024*512];   // U hi, k-major (64 MiB)
__device__ bf16  g_Ul[(size_t)64*1024*512];   // U lo
__device__ bf16  g_th[(size_t)64*32*512];     // t hi [b][n][d]
__device__ bf16  g_tl[(size_t)64*32*512];
__device__ bf16  g_ch[(size_t)64*32*1024];    // c hi [b][n][i]
__device__ bf16  g_cl[(size_t)64*32*1024];
__device__ float g_L [(size_t)64*1024*32];    // logits [b][i][n]
__device__ float g_V [(size_t)64*32*512];     // V [b][n][d]
__device__ float g_V0[64*512];
__device__ float g_Wt[(size_t)2048*512];      // W^T [z][d]

// ---------------- helpers ----------------
__device__ __forceinline__ uint32_t smem_u32(const void* p) {
    uint32_t a;
    asm("{ .reg .u64 t; cvta.to.shared.u64 t, %1; cvt.u32.u64 %0, t; }" : "=r"(a) : "l"(p));
    return a;
}
__device__ __forceinline__ void cpa16(uint32_t dst, const void* src) {
    asm volatile("cp.async.cg.shared.global [%0], [%1], 16;" :: "r"(dst), "l"(src));
}
__device__ __forceinline__ void cpa_commit() {
    asm volatile("cp.async.commit_group;" ::: "memory");
}
template<int N> __device__ __forceinline__ void cpa_wait() {
    asm volatile("cp.async.wait_group %0;" :: "n"(N) : "memory");
}
__device__ __forceinline__ void ldsm4(uint32_t* r, uint32_t a) {
    asm volatile("ldmatrix.sync.aligned.m8n8.x4.shared.b16 {%0,%1,%2,%3}, [%4];"
                 : "=r"(r[0]), "=r"(r[1]), "=r"(r[2]), "=r"(r[3]) : "r"(a));
}
__device__ __forceinline__ void ldsm4t(uint32_t* r, uint32_t a) {
    asm volatile("ldmatrix.sync.aligned.m8n8.x4.trans.shared.b16 {%0,%1,%2,%3}, [%4];"
                 : "=r"(r[0]), "=r"(r[1]), "=r"(r[2]), "=r"(r[3]) : "r"(a));
}
__device__ __forceinline__ void mma16816(float* c, const uint32_t* a, const uint32_t* b) {
    asm volatile(
        "mma.sync.aligned.m16n8k16.row.col.f32.bf16.bf16.f32 "
        "{%0,%1,%2,%3}, {%4,%5,%6,%7}, {%8,%9}, {%0,%1,%2,%3};"
        : "+f"(c[0]), "+f"(c[1]), "+f"(c[2]), "+f"(c[3])
        : "r"(a[0]), "r"(a[1]), "r"(a[2]), "r"(a[3]), "r"(b[0]), "r"(b[1]));
}
__device__ __forceinline__ bf16 bhi(float v) { return __float2bfloat16(v); }
__device__ __forceinline__ bf16 blo(float v, bf16 h) {
    return __float2bfloat16(v - __bfloat162float(h));
}

// ---------------- prep: U -> (Uh, Ul) split bf16 ----------------
__global__ void k_prep_u(const float* __restrict__ U) {
    size_t idx = (size_t)blockIdx.x * 256 + threadIdx.x;   // float4 index
    float4 v = ((const float4*)U)[idx];
    float vv[4] = {v.x, v.y, v.z, v.w};
    bf16 h[4], lo[4];
    #pragma unroll
    for (int j = 0; j < 4; j++) { h[j] = bhi(vv[j]); lo[j] = blo(vv[j], h[j]); }
    __nv_bfloat162* dh = (__nv_bfloat162*)(g_Uh + idx * 4);
    __nv_bfloat162* dl = (__nv_bfloat162*)(g_Ul + idx * 4);
    dh[0] = __nv_bfloat162(h[0], h[1]);  dh[1] = __nv_bfloat162(h[2], h[3]);
    dl[0] = __nv_bfloat162(lo[0], lo[1]); dl[1] = __nv_bfloat162(lo[2], lo[3]);
}

// ---------------- prep: Wt[z][d] = W[d][z] ----------------
__global__ void k_prep_w(const float* __restrict__ W) {
    int z0 = blockIdx.x * 32, d0 = blockIdx.y * 32;
    __shared__ float ts[32][33];
    int t = threadIdx.x, r = t >> 3, c4 = (t & 7) * 4;
    float4 v = *(const float4*)(W + (size_t)(d0 + r) * 2048 + z0 + c4);
    ts[r][c4 + 0] = v.x; ts[r][c4 + 1] = v.y; ts[r][c4 + 2] = v.z; ts[r][c4 + 3] = v.w;
    __syncthreads();
    float4 o = make_float4(ts[c4 + 0][r], ts[c4 + 1][r], ts[c4 + 2][r], ts[c4 + 3][r]);
    *(float4*)(g_Wt + (size_t)(z0 + r) * 512 + d0 + c4) = o;
}

// ---------------- V0[b,d] = (1/32) * sum_i U[b,i,d] ----------------
__global__ void k_sum0(const float* __restrict__ U) {
    int b = blockIdx.y, d0 = blockIdx.x * 64;
    int tid = threadIdx.x, dl = tid & 63, grp = tid >> 6;
    const float* base = U + (size_t)b * 1024 * 512 + d0 + dl;
    float a0 = 0.f, a1 = 0.f;
    #pragma unroll 4
    for (int i = grp; i < 1024; i += 8) {
        a0 += base[(size_t)i * 512];
        a1 += base[(size_t)(i + 4) * 512];
    }
    __shared__ float red[4][64];
    red[grp][dl] = a0 + a1;
    __syncthreads();
    if (tid < 64)
        g_V0[b * 512 + d0 + tid] =
            (red[0][tid] + red[1][tid] + red[2][tid] + red[3][tid]) * (1.0f / 32.0f);
}

// ---- out[b,n,dc] = squash_dc( sum_d V[b,n,d] * W[d, n*64+dc] ) ----
__global__ void __launch_bounds__(256) k_out(const float* __restrict__ W,
                                             float* __restrict__ out, int first) {
    int b0 = blockIdx.x * 8, n = blockIdx.y;
    int tid = threadIdx.x;
    __shared__ float V_s[8][512];
    __shared__ float W_s[64][65];
    __shared__ float sq[4][2][2];
    for (int idx = tid; idx < 8 * 512; idx += 256) {
        int bb = idx >> 9, d = idx & 511;
        V_s[bb][d] = first ? g_V0[(b0 + bb) * 512 + d]
                           : g_V[((size_t)(b0 + bb) * 32 + n) * 512 + d];
    }
    int dc = tid & 63, bq = tid >> 6;
    float a0 = 0.f, a1 = 0.f;
    for (int d0 = 0; d0 < 512; d0 += 64) {
        __syncthreads();
        for (int u = tid; u < 4096; u += 256) {
            int r = u >> 6, c = u & 63;
            W_s[r][c] = W[(size_t)(d0 + r) * 2048 + n * 64 + c];
        }
        __syncthreads();
        #pragma unroll 8
        for (int r = 0; r < 64; r++) {
            float w = W_s[r][dc];
            a0 = fmaf(V_s[bq][d0 + r], w, a0);
            a1 = fmaf(V_s[bq + 4][d0 + r], w, a1);
        }
    }
    float s0 = a0 * a0, s1 = a1 * a1;
    #pragma unroll
    for (int o = 16; o > 0; o >>= 1) {
        s0 += __shfl_xor_sync(0xffffffffu, s0, o);
        s1 += __shfl_xor_sync(0xffffffffu, s1, o);
    }
    int half = (tid >> 5) & 1;
    if ((tid & 31) == 0) { sq[bq][0][half] = s0; sq[bq][1][half] = s1; }
    __syncthreads();
    float inv0 = rsqrtf(sq[bq][0][0] + sq[bq][0][1] + EPSQ);
    float inv1 = rsqrtf(sq[bq][1][0] + sq[bq][1][1] + EPSQ);
    out[(size_t)(b0 + bq) * 2048 + n * 64 + dc]     = a0 * inv0;
    out[(size_t)(b0 + bq + 4) * 2048 + n * 64 + dc] = a1 * inv1;
}

// ---- t[b,n,d] = sum_dc Wt[n*64+dc][d] * out[b,n,dc] -> bf16 hi/lo ----
__global__ void __launch_bounds__(256) k_t(const float* __restrict__ out) {
    int n = blockIdx.x, b0 = blockIdx.y * 8;
    int t = threadIdx.x;
    __shared__ float o_s[8][64];
    for (int idx = t; idx < 512; idx += 256) {
        int bb = idx >> 6, dc = idx & 63;
        o_s[bb][dc] = out[(size_t)(b0 + bb) * 2048 + n * 64 + dc];
    }
    __syncthreads();
    const float* wbase = g_Wt + (size_t)n * 64 * 512;
    float acc[2][8];
    #pragma unroll
    for (int dd = 0; dd < 2; dd++)
        #pragma unroll
        for (int bb = 0; bb < 8; bb++) acc[dd][bb] = 0.f;
    #pragma unroll 4
    for (int dc = 0; dc < 64; dc++) {
        float w0 = wbase[(size_t)dc * 512 + t];
        float w1 = wbase[(size_t)dc * 512 + t + 256];
        #pragma unroll
        for (int bb = 0; bb < 8; bb++) {
            float o = o_s[bb][dc];
            acc[0][bb] = fmaf(w0, o, acc[0][bb]);
            acc[1][bb] = fmaf(w1, o, acc[1][bb]);
        }
    }
    #pragma unroll
    for (int bb = 0; bb < 8; bb++)
        #pragma unroll
        for (int dd = 0; dd < 2; dd++) {
            int d = t + dd * 256;
            size_t o = ((size_t)(b0 + bb) * 32 + n) * 512 + d;
            float v = acc[dd][bb];
            bf16 h = bhi(v);
            g_th[o] = h; g_tl[o] = blo(v, h);
        }
}

// ---- softmax over n per (b,i); emit c hi/lo bf16 [b][n][i] ----
__global__ void __launch_bounds__(128) k_softmax() {
    int ib = blockIdx.x, b = blockIdx.y, t = threadIdx.x;
    const float* lr = g_L + ((size_t)b * 1024 + ib * 128 + t) * 32;
    float v[32];
    #pragma unroll
    for (int g = 0; g < 8; g++) {
        float4 f = *(const float4*)(lr + g * 4);
        v[g * 4] = f.x; v[g * 4 + 1] = f.y; v[g * 4 + 2] = f.z; v[g * 4 + 3] = f.w;
    }
    float mx = v[0];
    #pragma unroll
    for (int n = 1; n < 32; n++) mx = fmaxf(mx, v[n]);
    float sm = 0.f;
    #pragma unroll
    for (int n = 0; n < 32; n++) { v[n] = __expf(v[n] - mx); sm += v[n]; }
    float inv = 1.0f / sm;
    __shared__ __align__(16) bf16 sh[32][128];
    __shared__ __align__(16) bf16 sl[32][128];
    #pragma unroll
    for (int n = 0; n < 32; n++) {
        float c = v[n] * inv;
        bf16 h = bhi(c);
        sh[n][t] = h; sl[n][t] = blo(c, h);
    }
    __syncthreads();
    #pragma unroll
    for (int k = 0; k < 4; k++) {
        int u = t + k * 128;
        int n = u >> 4, g = u & 15;
        size_t o = ((size_t)b * 32 + n) * 1024 + ib * 128 + g * 8;
        *(uint4*)&g_ch[o] = *(const uint4*)&sh[n][g * 8];
        *(uint4*)&g_cl[o] = *(const uint4*)&sl[n][g * 8];
    }
}

// ============ split-bf16 mma.sync GEMM (sm_80-baseline PTX) ============
// WHICH=0: L[b][i][n] = U . t^T      M=128/tile (8 tiles), N=32,  K=512
// WHICH=1: V[b][n][d] = c . U        M=32,  N=128/tile (4 tiles), K=1024
#define STAGE      40960
#define BIG_LO     16384
#define SMALLO     32768
#define SMALL_LO   36864
#define GEMM_SMEM  (2 * STAGE + 256)

template<int WHICH>
__global__ void __launch_bounds__(256, 1) k_gemm() {
    extern __shared__ char dsm[];
    uint32_t sb0 = (smem_u32(dsm) + 127) & ~127u;
    const int b = blockIdx.y, tile = blockIdx.x;
    const int t = threadIdx.x, w = t >> 5, l = t & 31;
    const int NC = WHICH ? 16 : 8;   // K/64

    float acc[2][2][4];
    #pragma unroll
    for (int mi = 0; mi < 2; mi++)
        #pragma unroll
        for (int ni = 0; ni < 2; ni++)
            #pragma unroll
            for (int q = 0; q < 4; q++) acc[mi][ni][q] = 0.f;

    auto load_chunk = [&](int c, int s) {
        uint32_t stg = sb0 + (uint32_t)s * STAGE;
        if (WHICH == 0) {
            // big = U tile [128 i][64 k], pitch 128B
            size_t a0 = ((size_t)b * 1024 + tile * 128) * 512 + (size_t)c * 64;
            #pragma unroll
            for (int u = t; u < 1024; u += 256) {
                int row = u >> 3, c16 = u & 7;
                size_t g = a0 + (size_t)row * 512 + c16 * 8;
                uint32_t d = stg + row * 128 + ((c16 * 16) ^ ((row & 7) << 4));
                cpa16(d, g_Uh + g);
                cpa16(d + BIG_LO, g_Ul + g);
            }
            // small = t tile [32 n][64 k], pitch 128B
            {
                int row = t >> 3, c16 = t & 7;
                size_t g = ((size_t)b * 32 + row) * 512 + (size_t)c * 64 + c16 * 8;
                uint32_t d = stg + SMALLO + row * 128 + ((c16 * 16) ^ ((row & 7) << 4));
                cpa16(d, g_th + g);
                cpa16(d + 4096, g_tl + g);
            }
        } else {
            // big = U tile [64 k(i)][128 d], pitch 256B
            size_t b0 = ((size_t)b * 1024 + (size_t)c * 64) * 512 + tile * 128;
            #pragma unroll
            for (int u = t; u < 1024; u += 256) {
                int row = u >> 4, c16 = u & 15;
                size_t g = b0 + (size_t)row * 512 + c16 * 8;
                uint32_t d = stg + row * 256 + ((c16 * 16) ^ ((row & 7) << 4));
                cpa16(d, g_Uh + g);
                cpa16(d + BIG_LO, g_Ul + g);
            }
            // small = c tile [32 n][64 k(i)], pitch 128B
            {
                int row = t >> 3, c16 = t & 7;
                size_t g = ((size_t)b * 32 + row) * 1024 + (size_t)c * 64 + c16 * 8;
                uint32_t d = stg + SMALLO + row * 128 + ((c16 * 16) ^ ((row & 7) << 4));
                cpa16(d, g_ch + g);
                cpa16(d + 4096, g_cl + g);
            }
        }
        cpa_commit();
    };

    auto compute = [&](int s) {
        uint32_t stg = sb0 + (uint32_t)s * STAGE;
        #pragma unroll
        for (int kk = 0; kk < 4; kk++) {
            uint32_t kb = kk * 32;   // bytes
            uint32_t aH[2][4], aL[2][4], bH[4], bL[4];
            if (WHICH == 0) {
                int mr = (w >> 1) * 32, nb = (w & 1) * 16;
                #pragma unroll
                for (int mi = 0; mi < 2; mi++) {
                    int row = mr + mi * 16 + (l & 7) + (l & 8);
                    uint32_t cb = kb + ((l >> 4) & 1) * 16;
                    uint32_t ad = stg + row * 128 + (cb ^ ((row & 7) << 4));
                    ldsm4(aH[mi], ad);
                    ldsm4(aL[mi], ad + BIG_LO);
                }
                {
                    int row = nb + (l & 7) + ((l >> 4) & 1) * 8;
                    uint32_t cb = kb + ((l >> 3) & 1) * 16;
                    uint32_t ad = stg + SMALLO + row * 128 + (cb ^ ((row & 7) << 4));
                    ldsm4(bH, ad);
                    ldsm4(bL, ad + 4096);
                }
            } else {
                #pragma unroll
                for (int mi = 0; mi < 2; mi++) {
                    int row = mi * 16 + (l & 7) + (l & 8);
                    uint32_t cb = kb + ((l >> 4) & 1) * 16;
                    uint32_t ad = stg + SMALLO + row * 128 + (cb ^ ((row & 7) << 4));
                    ldsm4(aH[mi], ad);
                    ldsm4(aL[mi], ad + 4096);
                }
                {
                    int krow = kk * 16 + (l & 7) + (l & 8);
                    uint32_t cb = w * 32 + ((l >> 4) & 1) * 16;
                    uint32_t ad = stg + krow * 256 + (cb ^ ((krow & 7) << 4));
                    ldsm4t(bH, ad);
                    ldsm4t(bL, ad + BIG_LO);
                }
            }
            #pragma unroll
            for (int mi = 0; mi < 2; mi++)
                #pragma unroll
                for (int ni = 0; ni < 2; ni++) {
                    mma16816(acc[mi][ni], aH[mi], &bH[ni * 2]);
                    mma16816(acc[mi][ni], aH[mi], &bL[ni * 2]);
                    mma16816(acc[mi][ni], aL[mi], &bH[ni * 2]);
                }
        }
    };

    load_chunk(0, 0);
    for (int c = 0; c < NC; c++) {
        if (c + 1 < NC) {
            load_chunk(c + 1, (c + 1) & 1);
            cpa_wait<1>();
        } else {
            cpa_wait<0>();
        }
        __syncthreads();
        compute(c & 1);
        __syncthreads();
    }

    // epilogue: direct global stores from C fragments
    if (WHICH == 0) {
        int mr = (w >> 1) * 32, nb = (w & 1) * 16;
        #pragma unroll
        for (int mi = 0; mi < 2; mi++) {
            int r0 = tile * 128 + mr + mi * 16 + (l >> 2);
            #pragma unroll
            for (int ni = 0; ni < 2; ni++) {
                int col = nb + ni * 8 + 2 * (l & 3);
                *(float2*)(g_L + ((size_t)b * 1024 + r0) * 32 + col) =
                    make_float2(acc[mi][ni][0], acc[mi][ni][1]);
                *(float2*)(g_L + ((size_t)b * 1024 + r0 + 8) * 32 + col) =
                    make_float2(acc[mi][ni][2], acc[mi][ni][3]);
            }
        }
    } else {
        #pragma unroll
        for (int mi = 0; mi < 2; mi++) {
            int n0 = mi * 16 + (l >> 2);
            #pragma unroll
            for (int ni = 0; ni < 2; ni++) {
                int d = tile * 128 + w * 16 + ni * 8 + 2 * (l & 3);
                *(float2*)(g_V + ((size_t)b * 32 + n0) * 512 + d) =
                    make_float2(acc[mi][ni][0], acc[mi][ni][1]);
                *(float2*)(g_V + ((size_t)b * 32 + n0 + 8) * 512 + d) =
                    make_float2(acc[mi][ni][2], acc[mi][ni][3]);
            }
        }
    }
}

// ---------------- launcher ----------------
extern "C" void kernel_launch(void* const* d_in, const int* in_sizes, int n_in,
                              void* d_out, int out_size) {
    const float* U = (const float*)d_in[0];  // [64,1024,512]
    const float* W = (const float*)d_in[1];  // [1,512,2048]
    float* out = (float*)d_out;              // [64,32,64]

    cudaFuncSetAttribute(k_gemm<0>, cudaFuncAttributeMaxDynamicSharedMemorySize, GEMM_SMEM);
    cudaFuncSetAttribute(k_gemm<1>, cudaFuncAttributeMaxDynamicSharedMemorySize, GEMM_SMEM);

    k_prep_u<<<32768, 256>>>(U);
    k_prep_w<<<dim3(64, 16), 256>>>(W);
    k_sum0  <<<dim3(8, 64), 256>>>(U);
    k_out   <<<dim3(8, 32), 256>>>(W, out, 1);            // iter 0 (uniform c)

    for (int it = 0; it < 2; it++) {
        k_t       <<<dim3(32, 8), 256>>>(out);
        k_gemm<0> <<<dim3(8, 64), 256, GEMM_SMEM>>>();    // logits
        k_softmax <<<dim3(8, 64), 128>>>();
        k_gemm<1> <<<dim3(4, 64), 256, GEMM_SMEM>>>();    // V = c . U
        k_out     <<<dim3(8, 32), 256>>>(W, out, 0);
    }
}